// round 1
// baseline (speedup 1.0000x reference)
#include <cuda_runtime.h>
#include <cstdint>

namespace {
constexpr int Bq = 8;
constexpr int Tq = 2048;
constexpr int Eq = 2048;
constexpr int TS = 64;    // s-tile per block
constexpr int TE = 128;   // e-tile per block
constexpr int TT = 32;    // t-chunk staged through smem

__device__ __forceinline__ unsigned long long pack2(float lo, float hi) {
    unsigned long long r;
    asm("mov.b64 %0, {%1, %2};"
        : "=l"(r) : "r"(__float_as_uint(lo)), "r"(__float_as_uint(hi)));
    return r;
}
__device__ __forceinline__ void unpack2(unsigned long long v, float& lo, float& hi) {
    unsigned int a, b;
    asm("mov.b64 {%0, %1}, %2;" : "=r"(a), "=r"(b) : "l"(v));
    lo = __uint_as_float(a);
    hi = __uint_as_float(b);
}
// Packed dual-FMA (FFMA2) — full-rate fp32 on sm_103a, only reachable via PTX.
__device__ __forceinline__ unsigned long long fma2(unsigned long long a,
                                                   unsigned long long b,
                                                   unsigned long long c) {
    unsigned long long d;
    asm("fma.rn.f32x2 %0, %1, %2, %3;" : "=l"(d) : "l"(a), "l"(b), "l"(c));
    return d;
}
}  // namespace

// out[b,s,e] = bias[s] + sum_{t<=s} x[b,t,e] * weight[s-t]
// Block: TS x TE output tile for one batch. 256 threads: tx (16) along e
// (8 floats = 4 f32x2 each), ty (16) along s (4 consecutive s each).
__global__ __launch_bounds__(256)
void toeplitz_conv_kernel(const float* __restrict__ x,
                          const float* __restrict__ weight,
                          const float* __restrict__ bias,
                          float* __restrict__ out) {
    __shared__ float ws[TS + Tq];   // front-padded with TS zeros: ws[TS+d]=weight[d]
    __shared__ float xs[TT][TE];

    const int e0  = blockIdx.x * TE;
    const int s0  = blockIdx.y * TS;
    const int b   = blockIdx.z;
    const int tid = threadIdx.x;
    const int tx  = tid & 15;   // e group
    const int ty  = tid >> 4;   // s group

    // Zero-padded weight table: index ws[TS + s - t]; s-t < 0 reads 0.
    for (int i = tid; i < TS + Tq; i += 256)
        ws[i] = (i < TS) ? 0.0f : weight[i - TS];

    // 4 s x 4 f32x2 (8 e) accumulators, seeded with bias[s] in both lanes.
    unsigned long long acc[4][4];
#pragma unroll
    for (int i = 0; i < 4; i++) {
        float bv = bias[s0 + ty * 4 + i];
        unsigned long long bp = pack2(bv, bv);
#pragma unroll
        for (int j = 0; j < 4; j++) acc[i][j] = bp;
    }

    const size_t x_base = ((size_t)b * Tq) * Eq + e0;
    const int t_end = s0 + TS;   // triangular cutoff: t in [0, s0+TS)

    for (int t0 = 0; t0 < t_end; t0 += TT) {
        __syncthreads();
        // Stage x[b, t0:t0+TT, e0:e0+TE] -> smem. 1024 float4s, 4 per thread.
#pragma unroll
        for (int k = 0; k < 4; k++) {
            int idx = tid + k * 256;
            int r = idx >> 5;          // TE/4 = 32 float4 per row
            int c = (idx & 31) << 2;
            *(float4*)&xs[r][c] =
                *(const float4*)&x[x_base + (size_t)(t0 + r) * Eq + c];
        }
        __syncthreads();

#pragma unroll 4
        for (int t = 0; t < TT; t++) {
            float4 xa = *(const float4*)&xs[t][tx * 8];
            float4 xb = *(const float4*)&xs[t][tx * 8 + 4];
            unsigned long long xp0 = pack2(xa.x, xa.y);
            unsigned long long xp1 = pack2(xa.z, xa.w);
            unsigned long long xp2 = pack2(xb.x, xb.y);
            unsigned long long xp3 = pack2(xb.z, xb.w);
            const int wbase = TS + s0 + ty * 4 - (t0 + t);
#pragma unroll
            for (int i = 0; i < 4; i++) {
                float wv = ws[wbase + i];                 // warp-broadcast LDS
                unsigned long long wp = pack2(wv, wv);
                acc[i][0] = fma2(xp0, wp, acc[i][0]);
                acc[i][1] = fma2(xp1, wp, acc[i][1]);
                acc[i][2] = fma2(xp2, wp, acc[i][2]);
                acc[i][3] = fma2(xp3, wp, acc[i][3]);
            }
        }
    }

#pragma unroll
    for (int i = 0; i < 4; i++) {
        const int s = s0 + ty * 4 + i;
        float v[8];
#pragma unroll
        for (int j = 0; j < 4; j++) unpack2(acc[i][j], v[2 * j], v[2 * j + 1]);
        float4* op = (float4*)&out[((size_t)b * Tq + s) * Eq + e0 + tx * 8];
        op[0] = make_float4(v[0], v[1], v[2], v[3]);
        op[1] = make_float4(v[4], v[5], v[6], v[7]);
    }
}

extern "C" void kernel_launch(void* const* d_in, const int* in_sizes, int n_in,
                              void* d_out, int out_size) {
    const float* x      = (const float*)d_in[0];
    const float* weight = (const float*)d_in[1];
    const float* bias   = (const float*)d_in[2];
    float* out          = (float*)d_out;

    dim3 grid(Eq / TE, Tq / TS, Bq);   // (16, 32, 8) = 4096 blocks
    toeplitz_conv_kernel<<<grid, 256>>>(x, weight, bias, out);
}

// round 4
// speedup vs baseline: 1.8330x; 1.8330x over previous
#include <cuda_runtime.h>
#include <cstdint>

namespace {
constexpr int Bq = 8;
constexpr int Tq = 2048;
constexpr int Eq = 2048;
constexpr int TS = 128;   // s-tile per block
constexpr int TE = 128;   // e-tile per block
constexpr int TT = 32;    // t-chunk staged through smem

__device__ __forceinline__ unsigned long long pack2(float lo, float hi) {
    unsigned long long r;
    asm("mov.b64 %0, {%1, %2};"
        : "=l"(r) : "r"(__float_as_uint(lo)), "r"(__float_as_uint(hi)));
    return r;
}
__device__ __forceinline__ void unpack2(unsigned long long v, float& lo, float& hi) {
    unsigned int a, b;
    asm("mov.b64 {%0, %1}, %2;" : "=r"(a), "=r"(b) : "l"(v));
    lo = __uint_as_float(a);
    hi = __uint_as_float(b);
}
// Packed dual-FMA (FFMA2) — full-rate fp32 on sm_103a, only reachable via PTX.
__device__ __forceinline__ unsigned long long fma2(unsigned long long a,
                                                   unsigned long long b,
                                                   unsigned long long c) {
    unsigned long long d;
    asm("fma.rn.f32x2 %0, %1, %2, %3;" : "=l"(d) : "l"(a), "l"(b), "l"(c));
    return d;
}
}  // namespace

// out[b,s,e] = bias[s] + sum_{t<=s} x[b,t,e] * weight[s-t]
// Block: TS(128) x TE(128) tile, 256 threads.
// Thread (tx = tid&7, ty = tid>>3): 4 consecutive s (ty*4+i), 16 e as 4
// interleaved float4 chunks (e = tx*4 + k*32) -> conflict-free LDS.128
// (8 distinct contiguous 16B addrs per instruction = 1 wavefront).
__global__ __launch_bounds__(256, 2)
void toeplitz_conv_kernel(const float* __restrict__ x,
                          const float* __restrict__ weight,
                          const float* __restrict__ bias,
                          float* __restrict__ out) {
    __shared__ __align__(16) float ws[TS + Tq];  // ws[TS+d] = weight[d], front zeros
    __shared__ __align__(16) float xs[TT][TE];

    const int e0  = blockIdx.x * TE;
    const int s0  = (gridDim.y - 1 - blockIdx.y) * TS;  // heavy blocks first
    const int b   = blockIdx.z;
    const int tid = threadIdx.x;
    const int tx  = tid & 7;    // e group (4 interleaved float4 chunks)
    const int ty  = tid >> 3;   // s group (4 consecutive s)

    for (int i = tid; i < TS + Tq; i += 256)
        ws[i] = (i < TS) ? 0.0f : weight[i - TS];

    // acc[i][p]: s = s0+ty*4+i, p = f32x2 index over 16 e values.
    unsigned long long acc[4][8];
#pragma unroll
    for (int i = 0; i < 4; i++) {
        float bv = bias[s0 + ty * 4 + i];
        unsigned long long bp = pack2(bv, bv);
#pragma unroll
        for (int p = 0; p < 8; p++) acc[i][p] = bp;
    }

    const size_t x_base = ((size_t)b * Tq) * Eq + e0;
    const int t_end = s0 + TS;  // triangular cutoff

    for (int t0 = 0; t0 < t_end; t0 += TT) {
        __syncthreads();
        // Stage x[b, t0:t0+TT, e0:e0+TE]: 1024 float4, 4 per thread.
#pragma unroll
        for (int k = 0; k < 4; k++) {
            int idx = tid + k * 256;
            int r = idx >> 5;           // 32 float4 per row
            int c = (idx & 31) << 2;
            *(float4*)&xs[r][c] =
                *(const float4*)&x[x_base + (size_t)(t0 + r) * Eq + c];
        }
        __syncthreads();

#pragma unroll
        for (int tt = 0; tt < TT; tt += 4) {
            // w tap window for t in [t0+tt, t0+tt+3], i in 0..3:
            // d = (s0+ty*4) - (t0+tt+j) + i  ->  ws[base - j + i], base 4-aligned.
            const int base = TS + s0 + ty * 4 - (t0 + tt);
            float wreg[8];
            *(float4*)&wreg[0] = *(const float4*)&ws[base - 4];
            *(float4*)&wreg[4] = *(const float4*)&ws[base];

#pragma unroll
            for (int j = 0; j < 4; j++) {
                const int t = tt + j;
                // 16 x values as 8 f32x2, no pack MOVs (direct 128b smem loads).
                unsigned long long xp[8];
#pragma unroll
                for (int k = 0; k < 4; k++) {
                    ulonglong2 v =
                        *(const ulonglong2*)&xs[t][tx * 4 + k * 32];
                    xp[2 * k]     = v.x;
                    xp[2 * k + 1] = v.y;
                }
#pragma unroll
                for (int i = 0; i < 4; i++) {
                    float wv = wreg[4 - j + i];     // static index post-unroll
                    unsigned long long wp = pack2(wv, wv);
#pragma unroll
                    for (int p = 0; p < 8; p++)
                        acc[i][p] = fma2(xp[p], wp, acc[i][p]);
                }
            }
        }
    }

#pragma unroll
    for (int i = 0; i < 4; i++) {
        const int s = s0 + ty * 4 + i;
        float* orow = &out[((size_t)b * Tq + s) * Eq + e0];
#pragma unroll
        for (int k = 0; k < 4; k++) {
            float v0, v1, v2, v3;
            unpack2(acc[i][2 * k],     v0, v1);
            unpack2(acc[i][2 * k + 1], v2, v3);
            *(float4*)&orow[tx * 4 + k * 32] = make_float4(v0, v1, v2, v3);
        }
    }
}

extern "C" void kernel_launch(void* const* d_in, const int* in_sizes, int n_in,
                              void* d_out, int out_size) {
    const float* x      = (const float*)d_in[0];
    const float* weight = (const float*)d_in[1];
    const float* bias   = (const float*)d_in[2];
    float* out          = (float*)d_out;

    dim3 grid(Eq / TE, Tq / TS, Bq);   // (16, 16, 8) = 2048 blocks
    toeplitz_conv_kernel<<<grid, 256>>>(x, weight, bias, out);
}

// round 8
// speedup vs baseline: 5.2660x; 2.8729x over previous
#include <cuda_runtime.h>
#include <cstdint>

namespace {
constexpr int Bq = 8, Tq = 2048, Eq = 2048;
constexpr int TS = 128;          // s tile (M)
constexpr int TE = 128;          // e tile (N)
constexpr int KT = 32;           // t chunk (4 x k8)
constexpr int PAD = 8;           // smem B row pad (words) -> conflict-free frags
constexpr int BROW = TE + PAD;   // 136 words per t-row
constexpr int WS_ELEMS = TS + Tq;

__device__ __forceinline__ float tf32r(float x) {   // round-to-nearest tf32
    float y; asm("cvt.rna.tf32.f32 %0, %1;" : "=f"(y) : "f"(x)); return y;
}
// Legacy tensor-core path: available on plain compute_103 (sm_80 baseline).
__device__ __forceinline__ void mma1688(float* d, const float* a, const float* b) {
    asm volatile(
        "mma.sync.aligned.m16n8k8.row.col.f32.tf32.tf32.f32 "
        "{%0,%1,%2,%3}, {%4,%5,%6,%7}, {%8,%9}, {%0,%1,%2,%3};"
        : "+f"(d[0]), "+f"(d[1]), "+f"(d[2]), "+f"(d[3])
        : "r"(__float_as_uint(a[0])), "r"(__float_as_uint(a[1])),
          "r"(__float_as_uint(a[2])), "r"(__float_as_uint(a[3])),
          "r"(__float_as_uint(b[0])), "r"(__float_as_uint(b[1])));
}
}  // namespace

// out[b,s,e] = bias[s] + sum_{t<=s} x[b,t,e]*weight[s-t]
// GEMM D[s,e] = A[s,t]*B[t,e]; A = lower-tri Toeplitz read straight from the
// zero-padded smem weight table (never materialized); B = x chunk in smem.
// 256 thr = 8 warps (2 m x 4 n), warp tile 64x32 = 4x4 m16n8k8 mmas.
__global__ __launch_bounds__(256, 2)
void toeplitz_mma_kernel(const float* __restrict__ x, const float* __restrict__ w,
                         const float* __restrict__ bias, float* __restrict__ out) {
    __shared__ float ws[WS_ELEMS];          // ws[TS+d] = tf32(weight[d]); front zeros
    __shared__ float bs[2][KT * BROW];      // double-buffered x chunk (t-major, +pad)

    const int tid = threadIdx.x, wid = tid >> 5, lane = tid & 31;
    const int grp = lane >> 2, tid4 = lane & 3;    // mma quad coords
    const int wm = wid >> 2, wn = wid & 3;          // warp grid 2(m) x 4(n)
    const int e0 = blockIdx.x * TE;
    const int s0 = ((int)gridDim.y - 1 - (int)blockIdx.y) * TS;  // heavy first
    const int b  = blockIdx.z;

    for (int i = tid; i < WS_ELEMS; i += 256)
        ws[i] = (i < TS) ? 0.0f : tf32r(w[i - TS]);

    float acc[4][4][4];                     // [mt][nt][frag]
#pragma unroll
    for (int mt = 0; mt < 4; mt++)
#pragma unroll
        for (int nt = 0; nt < 4; nt++)
#pragma unroll
            for (int f = 0; f < 4; f++) acc[mt][nt][f] = 0.0f;

    const int nchunk = (s0 + TS) / KT;      // triangular cutoff
    const size_t xbase = ((size_t)b * Tq) * Eq + e0;
    // Stage mapping: thread does rows r = wid + 8j (j=0..3), cols lane*4..+3.
    float4 pre[4];

    auto ldg = [&](int t0) {
#pragma unroll
        for (int j = 0; j < 4; j++)
            pre[j] = *(const float4*)&x[xbase + (size_t)(t0 + wid + 8 * j) * Eq + lane * 4];
    };
    auto sts = [&](int buf) {
#pragma unroll
        for (int j = 0; j < 4; j++) {
            float* p = &bs[buf][(wid + 8 * j) * BROW + lane * 4];
            p[0] = tf32r(pre[j].x); p[1] = tf32r(pre[j].y);
            p[2] = tf32r(pre[j].z); p[3] = tf32r(pre[j].w);
        }
    };

    ldg(0);
    sts(0);
    __syncthreads();

    for (int k = 0; k < nchunk; k++) {
        const int buf = k & 1;
        const int t0 = k * KT;
        if (k + 1 < nchunk) ldg(t0 + KT);   // prefetch next chunk to regs

#pragma unroll
        for (int kk = 0; kk < 4; kk++) {
            // A fragments straight from Toeplitz table (conflict-free broadcast).
            const int abase = TS + s0 + wm * 64 - t0 - kk * 8 + grp - tid4;
            float afr[4][4];
#pragma unroll
            for (int mt = 0; mt < 4; mt++) {
                const int i0 = abase + mt * 16;
                afr[mt][0] = ws[i0];        // A[grp][tid4]
                afr[mt][1] = ws[i0 + 8];    // A[grp+8][tid4]
                afr[mt][2] = ws[i0 - 4];    // A[grp][tid4+4]
                afr[mt][3] = ws[i0 + 4];    // A[grp+8][tid4+4]
            }
            // B fragments: B[k][n] = x[t0+k, e0+n]; banks 0..31 per LDS (pad=8).
            float bfr[4][2];
            const int brow = (kk * 8 + tid4) * BROW + wn * 32 + grp;
#pragma unroll
            for (int nt = 0; nt < 4; nt++) {
                bfr[nt][0] = bs[buf][brow + nt * 8];
                bfr[nt][1] = bs[buf][brow + nt * 8 + 4 * BROW];
            }
#pragma unroll
            for (int mt = 0; mt < 4; mt++)
#pragma unroll
                for (int nt = 0; nt < 4; nt++)
                    mma1688(acc[mt][nt], afr[mt], bfr[nt]);
        }

        __syncthreads();                    // everyone done reading bs[buf]
        if (k + 1 < nchunk) {
            sts(buf ^ 1);
            __syncthreads();                // next chunk visible
        }
    }

    // Epilogue: c0/c1 -> row grp, cols 2*tid4(+1); c2/c3 -> row grp+8.
#pragma unroll
    for (int mt = 0; mt < 4; mt++) {
        const int r0 = s0 + wm * 64 + mt * 16 + grp;
        const int r1 = r0 + 8;
        const float bv0 = bias[r0], bv1 = bias[r1];
        const int ec = e0 + wn * 32 + tid4 * 2;
#pragma unroll
        for (int nt = 0; nt < 4; nt++) {
            float2 v0 = make_float2(acc[mt][nt][0] + bv0, acc[mt][nt][1] + bv0);
            float2 v1 = make_float2(acc[mt][nt][2] + bv1, acc[mt][nt][3] + bv1);
            *(float2*)&out[((size_t)b * Tq + r0) * Eq + ec + nt * 8] = v0;
            *(float2*)&out[((size_t)b * Tq + r1) * Eq + ec + nt * 8] = v1;
        }
    }
}

extern "C" void kernel_launch(void* const* d_in, const int* in_sizes, int n_in,
                              void* d_out, int out_size) {
    const float* x      = (const float*)d_in[0];
    const float* weight = (const float*)d_in[1];
    const float* bias   = (const float*)d_in[2];
    float* out          = (float*)d_out;

    dim3 grid(Eq / TE, Tq / TS, Bq);   // (16, 16, 8) = 2048 blocks
    toeplitz_mma_kernel<<<grid, 256>>>(x, weight, bias, out);
}

// round 9
// speedup vs baseline: 5.7371x; 1.0895x over previous
#include <cuda_runtime.h>
#include <cstdint>

namespace {
constexpr int Bq = 8, Tq = 2048, Eq = 2048;
constexpr int TS = 128;          // s tile (M)
constexpr int TE = 128;          // e tile (N)
constexpr int KT = 32;           // t chunk (4 x k8)
constexpr int PAD = 8;           // smem B row pad (words) -> conflict-free frags
constexpr int BROW = TE + PAD;   // 136 words per t-row
constexpr int WS_ELEMS = TS + Tq;

__device__ __forceinline__ float tf32r(float x) {   // round-to-nearest tf32
    float y; asm("cvt.rna.tf32.f32 %0, %1;" : "=f"(y) : "f"(x)); return y;
}
// Legacy tensor-core path: available on plain compute_103 (sm_80 baseline).
__device__ __forceinline__ void mma1688(float* d, float a0, float a1, float a2,
                                        float a3, float b0, float b1) {
    asm volatile(
        "mma.sync.aligned.m16n8k8.row.col.f32.tf32.tf32.f32 "
        "{%0,%1,%2,%3}, {%4,%5,%6,%7}, {%8,%9}, {%0,%1,%2,%3};"
        : "+f"(d[0]), "+f"(d[1]), "+f"(d[2]), "+f"(d[3])
        : "r"(__float_as_uint(a0)), "r"(__float_as_uint(a1)),
          "r"(__float_as_uint(a2)), "r"(__float_as_uint(a3)),
          "r"(__float_as_uint(b0)), "r"(__float_as_uint(b1)));
}
}  // namespace

// out[b,s,e] = bias[s] + sum_{t<=s} x[b,t,e]*weight[s-t]
// GEMM D[s,e] = A[s,t]*B[t,e]; A = lower-tri Toeplitz. A-fragments come from a
// 22-register sliding window over the smem weight table (one broadcast LDS
// sweep per chunk, zero LDS in the kk loop); B = x chunk staged in smem.
// 256 thr = 8 warps (2 m x 4 n), warp tile 64x32 = 4x4 m16n8k8 mmas.
__global__ __launch_bounds__(256, 2)
void toeplitz_mma_kernel(const float* __restrict__ x, const float* __restrict__ w,
                         const float* __restrict__ bias, float* __restrict__ out) {
    __shared__ float ws[WS_ELEMS];          // ws[TS+d] = tf32(weight[d]); front zeros
    __shared__ float bs[2][KT * BROW];      // double-buffered x chunk (t-major, +pad)

    const int tid = threadIdx.x, wid = tid >> 5, lane = tid & 31;
    const int grp = lane >> 2, tid4 = lane & 3;    // mma quad coords
    const int wm = wid >> 2, wn = wid & 3;          // warp grid 2(m) x 4(n)
    const int e0 = blockIdx.x * TE;
    const int s0 = ((int)gridDim.y - 1 - (int)blockIdx.y) * TS;  // heavy first
    const int b  = blockIdx.z;

    for (int i = tid; i < WS_ELEMS; i += 256)
        ws[i] = (i < TS) ? 0.0f : tf32r(w[i - TS]);

    float acc[4][4][4];                     // [mt][nt][frag]
#pragma unroll
    for (int mt = 0; mt < 4; mt++)
#pragma unroll
        for (int nt = 0; nt < 4; nt++)
#pragma unroll
            for (int f = 0; f < 4; f++) acc[mt][nt][f] = 0.0f;

    const int nchunk = (s0 + TS) / KT;      // triangular cutoff
    const size_t xbase = ((size_t)b * Tq) * Eq + e0;
    // A-window anchor (word index for j=0 at t0=0): base0 - 28.
    const int wj0 = TS + s0 + wm * 64 + grp - tid4 - 28;
    float4 pre[4];

    auto ldg = [&](int t0) {
#pragma unroll
        for (int j = 0; j < 4; j++)
            pre[j] = *(const float4*)&x[xbase + (size_t)(t0 + wid + 8 * j) * Eq + lane * 4];
    };
    auto sts = [&](int buf) {
#pragma unroll
        for (int j = 0; j < 4; j++) {
            float* p = &bs[buf][(wid + 8 * j) * BROW + lane * 4];
            p[0] = tf32r(pre[j].x); p[1] = tf32r(pre[j].y);
            p[2] = tf32r(pre[j].z); p[3] = tf32r(pre[j].w);
        }
    };

    ldg(0);
    sts(0);
    __syncthreads();

    for (int k = 0; k < nchunk; k++) {
        const int buf = k & 1;
        const int t0 = k * KT;
        if (k + 1 < nchunk) ldg(t0 + KT);   // prefetch next chunk to regs

        // Toeplitz A window for this chunk: W[j] = ws[wj0 - t0 + 4j], j=0..21.
        // afr(mt,kk,f) = W[7 + 4*mt - 2*kk + {0,2,-1,1}] — static after unroll.
        float W[22];
        {
            const float* wp = &ws[wj0 - t0];
#pragma unroll
            for (int j = 0; j < 22; j++) W[j] = wp[4 * j];
        }

#pragma unroll
        for (int kk = 0; kk < 4; kk++) {
            // B fragments: B[k][n] = x[t0+k, e0+n]; banks 0..31 per LDS (pad=8).
            float bfr[4][2];
            const int brow = (kk * 8 + tid4) * BROW + wn * 32 + grp;
#pragma unroll
            for (int nt = 0; nt < 4; nt++) {
                bfr[nt][0] = bs[buf][brow + nt * 8];
                bfr[nt][1] = bs[buf][brow + nt * 8 + 4 * BROW];
            }
#pragma unroll
            for (int mt = 0; mt < 4; mt++) {
                const int j = 7 + 4 * mt - 2 * kk;
#pragma unroll
                for (int nt = 0; nt < 4; nt++)
                    mma1688(acc[mt][nt], W[j], W[j + 2], W[j - 1], W[j + 1],
                            bfr[nt][0], bfr[nt][1]);
            }
        }

        __syncthreads();                    // everyone done reading bs[buf]
        if (k + 1 < nchunk) {
            sts(buf ^ 1);
            __syncthreads();                // next chunk visible
        }
    }

    // Epilogue: c0/c1 -> row grp, cols 2*tid4(+1); c2/c3 -> row grp+8.
#pragma unroll
    for (int mt = 0; mt < 4; mt++) {
        const int r0 = s0 + wm * 64 + mt * 16 + grp;
        const int r1 = r0 + 8;
        const float bv0 = bias[r0], bv1 = bias[r1];
        const int ec = e0 + wn * 32 + tid4 * 2;
#pragma unroll
        for (int nt = 0; nt < 4; nt++) {
            float2 v0 = make_float2(acc[mt][nt][0] + bv0, acc[mt][nt][1] + bv0);
            float2 v1 = make_float2(acc[mt][nt][2] + bv1, acc[mt][nt][3] + bv1);
            *(float2*)&out[((size_t)b * Tq + r0) * Eq + ec + nt * 8] = v0;
            *(float2*)&out[((size_t)b * Tq + r1) * Eq + ec + nt * 8] = v1;
        }
    }
}

extern "C" void kernel_launch(void* const* d_in, const int* in_sizes, int n_in,
                              void* d_out, int out_size) {
    const float* x      = (const float*)d_in[0];
    const float* weight = (const float*)d_in[1];
    const float* bias   = (const float*)d_in[2];
    float* out          = (float*)d_out;

    dim3 grid(Eq / TE, Tq / TS, Bq);   // (16, 16, 8) = 2048 blocks
    toeplitz_mma_kernel<<<grid, 256>>>(x, weight, bias, out);
}

// round 10
// speedup vs baseline: 5.9602x; 1.0389x over previous
#include <cuda_runtime.h>
#include <cstdint>

namespace {
constexpr int Bq = 8, Tq = 2048, Eq = 2048;
constexpr int TS = 128;          // s tile (M)
constexpr int TE = 128;          // e tile (N)
constexpr int KT = 32;           // t chunk (4 x k8)
constexpr int PAD = 8;           // smem B row pad (words) -> conflict-free frags
constexpr int BROW = TE + PAD;   // 136 words per t-row
constexpr int WS_ELEMS = TS + Tq;
constexpr int NS = 3;            // cp.async ring stages
constexpr int STAGE_W = KT * BROW;                        // words per stage
constexpr int SMEM_BYTES = (WS_ELEMS + NS * STAGE_W) * 4; // 60928 B

// x is fed to HMMA as raw fp32 (hardware truncates to tf32, RZ). Mean relative
// shrink of |x| is 2^-11 * ln2 ~= 3.38e-4; fold the compensation into w.
constexpr float XCOMP = 1.000338f;

__device__ __forceinline__ float tf32r(float x) {   // round-to-nearest tf32
    float y; asm("cvt.rna.tf32.f32 %0, %1;" : "=f"(y) : "f"(x)); return y;
}
__device__ __forceinline__ uint32_t smem_u32(const void* p) {
    return (uint32_t)__cvta_generic_to_shared(p);
}
__device__ __forceinline__ void cp16(uint32_t dst, const void* src) {
    asm volatile("cp.async.cg.shared.global [%0], [%1], 16;"
                 :: "r"(dst), "l"(src));
}
__device__ __forceinline__ void cp_commit() {
    asm volatile("cp.async.commit_group;");
}
template <int N> __device__ __forceinline__ void cp_wait() {
    asm volatile("cp.async.wait_group %0;" :: "n"(N));
}
// Legacy tensor-core path: available on plain compute_103 (sm_80 baseline).
__device__ __forceinline__ void mma1688(float* d, float a0, float a1, float a2,
                                        float a3, float b0, float b1) {
    asm volatile(
        "mma.sync.aligned.m16n8k8.row.col.f32.tf32.tf32.f32 "
        "{%0,%1,%2,%3}, {%4,%5,%6,%7}, {%8,%9}, {%0,%1,%2,%3};"
        : "+f"(d[0]), "+f"(d[1]), "+f"(d[2]), "+f"(d[3])
        : "r"(__float_as_uint(a0)), "r"(__float_as_uint(a1)),
          "r"(__float_as_uint(a2)), "r"(__float_as_uint(a3)),
          "r"(__float_as_uint(b0)), "r"(__float_as_uint(b1)));
}
}  // namespace

// out[b,s,e] = bias[s] + sum_{t<=s} x[b,t,e]*weight[s-t]
// GEMM D[s,e] = A[s,t]*B[t,e]; A = lower-tri Toeplitz from a 22-reg sliding
// window over the smem weight table; B = x staged by cp.async (raw fp32, HW
// tf32-truncation compensated in w). 3-stage ring, one barrier per chunk.
// 256 thr = 8 warps (2 m x 4 n), warp tile 64x32 = 4x4 m16n8k8 mmas.
__global__ __launch_bounds__(256, 2)
void toeplitz_mma_kernel(const float* __restrict__ x, const float* __restrict__ w,
                         const float* __restrict__ bias, float* __restrict__ out) {
    extern __shared__ float sm[];
    float* ws = sm;                          // ws[TS+d] = tf32(w[d]*XCOMP); front 0
    float* bs = sm + WS_ELEMS;               // NS stages of KT x BROW (t-major)

    const int tid = threadIdx.x, wid = tid >> 5, lane = tid & 31;
    const int grp = lane >> 2, tid4 = lane & 3;     // mma quad coords
    const int wm = wid >> 2, wn = wid & 3;          // warp grid 2(m) x 4(n)
    const int e0 = blockIdx.x * TE;
    const int s0 = ((int)gridDim.y - 1 - (int)blockIdx.y) * TS;  // heavy first
    const int b  = blockIdx.z;

    for (int i = tid; i < WS_ELEMS; i += 256)
        ws[i] = (i < TS) ? 0.0f : tf32r(w[i - TS] * XCOMP);
    __syncthreads();   // ws visible before first consume (cp.async overlaps)

    float acc[4][4][4];                      // [mt][nt][frag]
#pragma unroll
    for (int mt = 0; mt < 4; mt++)
#pragma unroll
        for (int nt = 0; nt < 4; nt++)
#pragma unroll
            for (int f = 0; f < 4; f++) acc[mt][nt][f] = 0.0f;

    const int nchunk = (s0 + TS) / KT;       // triangular cutoff (>= 4)
    const size_t xbase = ((size_t)b * Tq) * Eq + e0;
    const int wj0 = TS + s0 + wm * 64 + grp - tid4 - 28;  // A-window anchor
    const int bbase = wn * 32 + grp;

    // Stage copy: thread owns rows (wid + 8j), 16B at word col lane*4.
    auto issue = [&](int k) {
        const int t0 = k * KT;
        float* stg = bs + (k % NS) * STAGE_W;
#pragma unroll
        for (int j = 0; j < 4; j++) {
            const int r = wid + 8 * j;
            cp16(smem_u32(&stg[r * BROW + lane * 4]),
                 &x[xbase + (size_t)(t0 + r) * Eq + lane * 4]);
        }
        cp_commit();
    };

    issue(0);
    issue(1);

    for (int k = 0; k < nchunk; k++) {
        // Ensure chunk k landed (groups complete in order; k+1 may stay pending).
        if (k + 1 < nchunk) cp_wait<1>(); else cp_wait<0>();
        __syncthreads();   // publishes chunk k; proves consume(k-1) finished
        if (k + 2 < nchunk) issue(k + 2);    // overwrites chunk k-1's stage: safe

        const float* stg = bs + (k % NS) * STAGE_W;

        // Toeplitz A window: W[j] = ws[wj0 - t0 + 4j], j=0..21.
        // afr(mt,kk,f) = W[7 + 4*mt - 2*kk + {0,2,-1,1}] — static after unroll.
        float W[22];
        {
            const float* wp = &ws[wj0 - k * KT];
#pragma unroll
            for (int j = 0; j < 22; j++) W[j] = wp[4 * j];
        }

#pragma unroll
        for (int kk = 0; kk < 4; kk++) {
            float bfr[4][2];
            const float* bp = &stg[(kk * 8 + tid4) * BROW + bbase];
#pragma unroll
            for (int nt = 0; nt < 4; nt++) {
                bfr[nt][0] = bp[nt * 8];
                bfr[nt][1] = bp[nt * 8 + 4 * BROW];
            }
#pragma unroll
            for (int mt = 0; mt < 4; mt++) {
                const int j = 7 + 4 * mt - 2 * kk;
#pragma unroll
                for (int nt = 0; nt < 4; nt++)
                    mma1688(acc[mt][nt], W[j], W[j + 2], W[j - 1], W[j + 1],
                            bfr[nt][0], bfr[nt][1]);
            }
        }
    }

    // Epilogue: c0/c1 -> row grp, cols 2*tid4(+1); c2/c3 -> row grp+8.
#pragma unroll
    for (int mt = 0; mt < 4; mt++) {
        const int r0 = s0 + wm * 64 + mt * 16 + grp;
        const int r1 = r0 + 8;
        const float bv0 = bias[r0], bv1 = bias[r1];
        const int ec = e0 + wn * 32 + tid4 * 2;
#pragma unroll
        for (int nt = 0; nt < 4; nt++) {
            float2 v0 = make_float2(acc[mt][nt][0] + bv0, acc[mt][nt][1] + bv0);
            float2 v1 = make_float2(acc[mt][nt][2] + bv1, acc[mt][nt][3] + bv1);
            *(float2*)&out[((size_t)b * Tq + r0) * Eq + ec + nt * 8] = v0;
            *(float2*)&out[((size_t)b * Tq + r1) * Eq + ec + nt * 8] = v1;
        }
    }
}

extern "C" void kernel_launch(void* const* d_in, const int* in_sizes, int n_in,
                              void* d_out, int out_size) {
    const float* x      = (const float*)d_in[0];
    const float* weight = (const float*)d_in[1];
    const float* bias   = (const float*)d_in[2];
    float* out          = (float*)d_out;

    static bool attr_set = false;
    if (!attr_set) {
        cudaFuncSetAttribute(toeplitz_mma_kernel,
                             cudaFuncAttributeMaxDynamicSharedMemorySize,
                             SMEM_BYTES);
        attr_set = true;
    }
    dim3 grid(Eq / TE, Tq / TS, Bq);   // (16, 16, 8) = 2048 blocks
    toeplitz_mma_kernel<<<grid, 256, SMEM_BYTES>>>(x, weight, bias, out);
}

// round 11
// speedup vs baseline: 6.5716x; 1.1026x over previous
#include <cuda_runtime.h>
#include <cstdint>

namespace {
constexpr int Bq = 8, Tq = 2048, Eq = 2048;
constexpr int TS = 128;          // s tile (M)
constexpr int TE = 64;           // e tile (N)
constexpr int KT = 32;           // t chunk (4 x k8)
constexpr int PAD = 8;           // smem B row pad (words) -> conflict-free frags
constexpr int BROW = TE + PAD;   // 72 words per t-row (72 mod 32 = 8)
constexpr int WS_ELEMS = TS + Tq;
constexpr int NS = 4;            // cp.async ring stages (prefetch depth 3)
constexpr int STAGE_W = KT * BROW;                        // 2304 words
constexpr int SMEM_BYTES = (WS_ELEMS + NS * STAGE_W) * 4; // 45568 B

// x is fed to HMMA as raw fp32 (hardware truncates to tf32, RZ). Mean relative
// shrink of |x| is 2^-11 * ln2 ~= 3.38e-4; fold the compensation into w.
constexpr float XCOMP = 1.000338f;

__device__ __forceinline__ float tf32r(float x) {   // round-to-nearest tf32
    float y; asm("cvt.rna.tf32.f32 %0, %1;" : "=f"(y) : "f"(x)); return y;
}
__device__ __forceinline__ uint32_t smem_u32(const void* p) {
    return (uint32_t)__cvta_generic_to_shared(p);
}
__device__ __forceinline__ void cp16(uint32_t dst, const void* src) {
    asm volatile("cp.async.cg.shared.global [%0], [%1], 16;"
                 :: "r"(dst), "l"(src));
}
__device__ __forceinline__ void cp_commit() {
    asm volatile("cp.async.commit_group;");
}
template <int N> __device__ __forceinline__ void cp_wait() {
    asm volatile("cp.async.wait_group %0;" :: "n"(N));
}
// Legacy tensor-core path: available on plain compute_103 (sm_80 baseline).
__device__ __forceinline__ void mma1688(float* d, float a0, float a1, float a2,
                                        float a3, float b0, float b1) {
    asm volatile(
        "mma.sync.aligned.m16n8k8.row.col.f32.tf32.tf32.f32 "
        "{%0,%1,%2,%3}, {%4,%5,%6,%7}, {%8,%9}, {%0,%1,%2,%3};"
        : "+f"(d[0]), "+f"(d[1]), "+f"(d[2]), "+f"(d[3])
        : "r"(__float_as_uint(a0)), "r"(__float_as_uint(a1)),
          "r"(__float_as_uint(a2)), "r"(__float_as_uint(a3)),
          "r"(__float_as_uint(b0)), "r"(__float_as_uint(b1)));
}
}  // namespace

// out[b,s,e] = bias[s] + sum_{t<=s} x[b,t,e]*weight[s-t]
// GEMM D[s,e] = A[s,t]*B[t,e]; A = lower-tri Toeplitz from a 22-reg sliding
// window over the smem weight table; B = x staged by cp.async (raw fp32, HW
// tf32-truncation compensated in w). 4-stage ring, one barrier per chunk.
// Small CTA (128 thr, 4 warps 2m x 2n, warp tile 64x32) -> 4 independent
// barrier domains per SM so barrier stalls are covered by sibling CTAs.
__global__ __launch_bounds__(128, 4)
void toeplitz_mma_kernel(const float* __restrict__ x, const float* __restrict__ w,
                         const float* __restrict__ bias, float* __restrict__ out) {
    extern __shared__ float sm[];
    float* ws = sm;                          // ws[TS+d] = tf32(w[d]*XCOMP); front 0
    float* bs = sm + WS_ELEMS;               // NS stages of KT x BROW (t-major)

    const int tid = threadIdx.x, wid = tid >> 5, lane = tid & 31;
    const int grp = lane >> 2, tid4 = lane & 3;     // mma quad coords
    const int wm = wid >> 1, wn = wid & 1;          // warp grid 2(m) x 2(n)
    const int e0 = blockIdx.x * TE;
    const int s0 = ((int)gridDim.y - 1 - (int)blockIdx.y) * TS;  // heavy first
    const int b  = blockIdx.z;

    // Bounded prologue: this CTA only reads ws[0 .. s0+255].
    const int ws_need = min(WS_ELEMS, s0 + 2 * TS);
    for (int i = tid; i < ws_need; i += 128)
        ws[i] = (i < TS) ? 0.0f : tf32r(w[i - TS] * XCOMP);
    __syncthreads();   // ws visible before first consume (cp.async overlaps)

    float acc[4][4][4];                      // [mt][nt][frag]
#pragma unroll
    for (int mt = 0; mt < 4; mt++)
#pragma unroll
        for (int nt = 0; nt < 4; nt++)
#pragma unroll
            for (int f = 0; f < 4; f++) acc[mt][nt][f] = 0.0f;

    const int nchunk = (s0 + TS) / KT;       // triangular cutoff (>= 4)
    const size_t xbase = ((size_t)b * Tq) * Eq + e0;
    const int wj0 = TS + s0 + wm * 64 + grp - tid4 - 28;  // A-window anchor
    const int bbase = wn * 32 + grp;
    const int srow = tid >> 4;               // stage row base (0..7)
    const int scol = (tid & 15) * 4;         // stage word col (16B granule)

    // Stage copy: 32 rows x 64 cols; thread owns rows srow+8j, one 16B each.
    auto issue = [&](int k) {
        const int t0 = k * KT;
        float* stg = bs + (k & (NS - 1)) * STAGE_W;
#pragma unroll
        for (int j = 0; j < 4; j++) {
            const int r = srow + 8 * j;
            cp16(smem_u32(&stg[r * BROW + scol]),
                 &x[xbase + (size_t)(t0 + r) * Eq + scol]);
        }
        cp_commit();
    };

    issue(0);
    issue(1);
    issue(2);

    for (int k = 0; k < nchunk; k++) {
        // Chunk k must have landed; newer groups may stay pending.
        const int ahead = nchunk - 1 - k;    // issued beyond k (capped at 2)
        if (ahead >= 2)      cp_wait<2>();
        else if (ahead == 1) cp_wait<1>();
        else                 cp_wait<0>();
        __syncthreads();   // publishes chunk k; proves consume(k-1) finished
        if (k + 3 < nchunk) issue(k + 3);    // overwrites chunk k-1's stage: safe

        const float* stg = bs + (k & (NS - 1)) * STAGE_W;

        // Toeplitz A window: W[j] = ws[wj0 - t0 + 4j], j=0..21.
        // afr(mt,kk,f) = W[7 + 4*mt - 2*kk + {0,2,-1,1}] — static after unroll.
        float W[22];
        {
            const float* wp = &ws[wj0 - k * KT];
#pragma unroll
            for (int j = 0; j < 22; j++) W[j] = wp[4 * j];
        }

#pragma unroll
        for (int kk = 0; kk < 4; kk++) {
            float bfr[4][2];
            const float* bp = &stg[(kk * 8 + tid4) * BROW + bbase];
#pragma unroll
            for (int nt = 0; nt < 4; nt++) {
                bfr[nt][0] = bp[nt * 8];
                bfr[nt][1] = bp[nt * 8 + 4 * BROW];
            }
#pragma unroll
            for (int mt = 0; mt < 4; mt++) {
                const int j = 7 + 4 * mt - 2 * kk;
#pragma unroll
                for (int nt = 0; nt < 4; nt++)
                    mma1688(acc[mt][nt], W[j], W[j + 2], W[j - 1], W[j + 1],
                            bfr[nt][0], bfr[nt][1]);
            }
        }
    }

    // Epilogue: c0/c1 -> row grp, cols 2*tid4(+1); c2/c3 -> row grp+8.
#pragma unroll
    for (int mt = 0; mt < 4; mt++) {
        const int r0 = s0 + wm * 64 + mt * 16 + grp;
        const int r1 = r0 + 8;
        const float bv0 = bias[r0], bv1 = bias[r1];
        const int ec = e0 + wn * 32 + tid4 * 2;
#pragma unroll
        for (int nt = 0; nt < 4; nt++) {
            float2 v0 = make_float2(acc[mt][nt][0] + bv0, acc[mt][nt][1] + bv0);
            float2 v1 = make_float2(acc[mt][nt][2] + bv1, acc[mt][nt][3] + bv1);
            *(float2*)&out[((size_t)b * Tq + r0) * Eq + ec + nt * 8] = v0;
            *(float2*)&out[((size_t)b * Tq + r1) * Eq + ec + nt * 8] = v1;
        }
    }
}

extern "C" void kernel_launch(void* const* d_in, const int* in_sizes, int n_in,
                              void* d_out, int out_size) {
    const float* x      = (const float*)d_in[0];
    const float* weight = (const float*)d_in[1];
    const float* bias   = (const float*)d_in[2];
    float* out          = (float*)d_out;

    static bool attr_set = false;
    if (!attr_set) {
        cudaFuncSetAttribute(toeplitz_mma_kernel,
                             cudaFuncAttributeMaxDynamicSharedMemorySize,
                             SMEM_BYTES);
        attr_set = true;
    }
    dim3 grid(Eq / TE, Tq / TS, Bq);   // (32, 16, 8) = 4096 blocks
    toeplitz_mma_kernel<<<grid, 128, SMEM_BYTES>>>(x, weight, bias, out);
}